// round 1
// baseline (speedup 1.0000x reference)
#include <cuda_runtime.h>
#include <cuda_bf16.h>

// ---------------- problem constants ----------------
#define L_SEQ   1024
#define DMODEL  1024
#define DINNER  2048
#define NSTATE  16
#define DTRANK  64
#define XDBL_W  96        // DTRANK + 2*NSTATE
#define WIN_N   4096      // 2*DINNER

// ---------------- scratch (__device__ globals; no allocation) ----------------
__device__ float g_xr[L_SEQ * WIN_N];       // x @ W_in   [1024,4096]
__device__ float g_xc[L_SEQ * DINNER];      // silu(conv) [1024,2048]
__device__ float g_xdbl[L_SEQ * XDBL_W];    // [1024,96]
__device__ float g_delta[L_SEQ * DINNER];   // [1024,2048]
__device__ float g_yg[L_SEQ * DINNER];      // gated scan output [1024,2048]

// ---------------- generic 128x128x8 SGEMM (dims must divide evenly) ----------
// C[M,N] = A[M,K] @ B[K,N], row-major, fp32
template <int WRITE_TO_OUT>
__global__ __launch_bounds__(256) void sgemm128(const float* __restrict__ A,
                                                const float* __restrict__ B,
                                                float* __restrict__ C,
                                                int M, int N, int K) {
    constexpr int BM = 128, BN = 128, BK = 8, TM = 8, TN = 8;
    __shared__ float As[BK][BM];
    __shared__ float Bs[BK][BN];

    const int tid = threadIdx.x;
    const int tr  = tid / 16;           // 0..15
    const int tc  = tid % 16;           // 0..15
    const int blockRow = blockIdx.y * BM;
    const int blockCol = blockIdx.x * BN;

    const int aRow = tid >> 1;          // 0..127
    const int aCol = (tid & 1) * 4;     // 0 or 4
    const int bRow = tid >> 5;          // 0..7
    const int bCol = (tid & 31) * 4;    // 0..124

    float acc[TM][TN];
    #pragma unroll
    for (int i = 0; i < TM; i++)
        #pragma unroll
        for (int j = 0; j < TN; j++) acc[i][j] = 0.f;

    for (int k0 = 0; k0 < K; k0 += BK) {
        float4 a = *reinterpret_cast<const float4*>(&A[(size_t)(blockRow + aRow) * K + k0 + aCol]);
        As[aCol + 0][aRow] = a.x;
        As[aCol + 1][aRow] = a.y;
        As[aCol + 2][aRow] = a.z;
        As[aCol + 3][aRow] = a.w;
        float4 b = *reinterpret_cast<const float4*>(&B[(size_t)(k0 + bRow) * N + blockCol + bCol]);
        *reinterpret_cast<float4*>(&Bs[bRow][bCol]) = b;
        __syncthreads();

        #pragma unroll
        for (int k = 0; k < BK; k++) {
            float rm[TM], rn[TN];
            #pragma unroll
            for (int i = 0; i < TM; i++) rm[i] = As[k][tr * TM + i];
            #pragma unroll
            for (int j = 0; j < TN; j++) rn[j] = Bs[k][tc * TN + j];
            #pragma unroll
            for (int i = 0; i < TM; i++)
                #pragma unroll
                for (int j = 0; j < TN; j++) acc[i][j] = fmaf(rm[i], rn[j], acc[i][j]);
        }
        __syncthreads();
    }

    #pragma unroll
    for (int i = 0; i < TM; i++) {
        float* crow = &C[(size_t)(blockRow + tr * TM + i) * N + blockCol + tc * TN];
        #pragma unroll
        for (int j = 0; j < TN; j += 4) {
            float4 v = make_float4(acc[i][j], acc[i][j + 1], acc[i][j + 2], acc[i][j + 3]);
            *reinterpret_cast<float4*>(&crow[j]) = v;
        }
    }
}

// ---------------- causal depthwise conv (K=4) + SiLU ------------------------
__global__ __launch_bounds__(256) void conv_silu_kernel(const float* __restrict__ conv_w,
                                                        const float* __restrict__ conv_b) {
    int idx = blockIdx.x * blockDim.x + threadIdx.x;   // t*2048 + d
    int t = idx >> 11;
    int d = idx & (DINNER - 1);
    float acc = conv_b[d];
    #pragma unroll
    for (int k = 0; k < 4; k++) {
        int tt = t - 3 + k;
        if (tt >= 0) acc = fmaf(g_xr[(size_t)tt * WIN_N + d], conv_w[d * 4 + k], acc);
    }
    float s = acc / (1.f + __expf(-acc));   // silu
    g_xc[idx] = s;
}

// ---------------- x_conv @ W_x -> x_dbl [1024,96] ---------------------------
// 4 t-rows per block; 128 threads (lanes 0..95 produce outputs)
__global__ __launch_bounds__(128) void xdbl_kernel(const float* __restrict__ Wx) {
    constexpr int TPER = 4;
    __shared__ float row[TPER * DINNER];   // 32 KB
    const int t0 = blockIdx.x * TPER;
    for (int i = threadIdx.x; i < TPER * DINNER; i += 128)
        row[i] = g_xc[(size_t)t0 * DINNER + i];
    __syncthreads();

    const int j = threadIdx.x;
    if (j < XDBL_W) {
        float acc[TPER] = {0.f, 0.f, 0.f, 0.f};
        #pragma unroll 4
        for (int k = 0; k < DINNER; k++) {
            float w = Wx[k * XDBL_W + j];
            #pragma unroll
            for (int tt = 0; tt < TPER; tt++)
                acc[tt] = fmaf(row[tt * DINNER + k], w, acc[tt]);
        }
        #pragma unroll
        for (int tt = 0; tt < TPER; tt++)
            g_xdbl[(size_t)(t0 + tt) * XDBL_W + j] = acc[tt];
    }
}

// ---------------- delta = softplus(dt @ W_dt + b_dt) ------------------------
// grid (DINNER/256, L/16); each thread: fixed d, 16 t-rows in registers
__global__ __launch_bounds__(256) void delta_kernel(const float* __restrict__ Wdt,
                                                    const float* __restrict__ bdt) {
    constexpr int TPER = 16;
    __shared__ float sdt[TPER][DTRANK];
    const int d  = blockIdx.x * 256 + threadIdx.x;
    const int t0 = blockIdx.y * TPER;

    for (int i = threadIdx.x; i < TPER * DTRANK; i += 256) {
        int tt = i / DTRANK, k = i % DTRANK;
        sdt[tt][k] = g_xdbl[(size_t)(t0 + tt) * XDBL_W + k];
    }
    __syncthreads();

    float acc[TPER];
    float b = bdt[d];
    #pragma unroll
    for (int tt = 0; tt < TPER; tt++) acc[tt] = b;

    #pragma unroll 4
    for (int k = 0; k < DTRANK; k++) {
        float w = Wdt[k * DINNER + d];
        #pragma unroll
        for (int tt = 0; tt < TPER; tt++)
            acc[tt] = fmaf(sdt[tt][k], w, acc[tt]);
    }

    #pragma unroll
    for (int tt = 0; tt < TPER; tt++) {
        float x = acc[tt];
        float sp = (x > 20.f) ? x : log1pf(__expf(x));
        g_delta[(size_t)(t0 + tt) * DINNER + d] = sp;
    }
}

// ---------------- selective scan + skip + gate ------------------------------
// one thread per (d, n); 16-lane groups per channel; 2 channels/warp
__global__ __launch_bounds__(256) void scan_kernel(const float* __restrict__ A_log,
                                                   const float* __restrict__ Dvec) {
    const int gtid = blockIdx.x * blockDim.x + threadIdx.x;
    const int warp = gtid >> 5;
    const int lane = threadIdx.x & 31;
    const int grp  = lane >> 4;           // 0/1: which channel in warp
    const int n    = lane & 15;           // state index
    const int d    = warp * 2 + grp;      // channel 0..2047

    const float A  = -__expf(A_log[d * NSTATE + n]);
    const float Dd = Dvec[d];
    float h = 0.f;

    for (int t = 0; t < L_SEQ; t++) {
        const float dl = g_delta[(size_t)t * DINNER + d];
        const float u  = g_xc[(size_t)t * DINNER + d];
        const float Bn = g_xdbl[(size_t)t * XDBL_W + DTRANK + n];
        const float Cn = g_xdbl[(size_t)t * XDBL_W + DTRANK + NSTATE + n];

        const float dA = __expf(dl * A);
        h = fmaf(dA, h, dl * Bn * u);

        float p = h * Cn;
        p += __shfl_xor_sync(0xffffffffu, p, 8, 16);
        p += __shfl_xor_sync(0xffffffffu, p, 4, 16);
        p += __shfl_xor_sync(0xffffffffu, p, 2, 16);
        p += __shfl_xor_sync(0xffffffffu, p, 1, 16);

        if (n == 0) {
            const float r = g_xr[(size_t)t * WIN_N + DINNER + d];
            const float y = fmaf(u, Dd, p);
            const float gate = r / (1.f + __expf(-r));
            g_yg[(size_t)t * DINNER + d] = y * gate;
        }
    }
}

// ---------------- launcher ----------------
extern "C" void kernel_launch(void* const* d_in, const int* in_sizes, int n_in,
                              void* d_out, int out_size) {
    const float* x      = (const float*)d_in[0];   // [1,1024,1024]
    const float* W_in   = (const float*)d_in[1];   // [1024,4096]
    const float* conv_w = (const float*)d_in[2];   // [2048,4]
    const float* conv_b = (const float*)d_in[3];   // [2048]
    const float* W_x    = (const float*)d_in[4];   // [2048,96]
    const float* W_dt   = (const float*)d_in[5];   // [64,2048]
    const float* b_dt   = (const float*)d_in[6];   // [2048]
    const float* A_log  = (const float*)d_in[7];   // [2048,16]
    const float* Dv     = (const float*)d_in[8];   // [2048]
    const float* W_out  = (const float*)d_in[9];   // [2048,1024]
    float* out = (float*)d_out;                    // [1024,1024]

    float* xr;    cudaGetSymbolAddress((void**)&xr,    g_xr);
    float* yg;    cudaGetSymbolAddress((void**)&yg,    g_yg);

    // 1) x @ W_in -> g_xr  (M=1024, N=4096, K=1024)
    {
        dim3 grid(WIN_N / 128, L_SEQ / 128);
        sgemm128<0><<<grid, 256>>>(x, W_in, xr, L_SEQ, WIN_N, DMODEL);
    }
    // 2) causal conv + silu -> g_xc
    conv_silu_kernel<<<(L_SEQ * DINNER) / 256, 256>>>(conv_w, conv_b);
    // 3) x_conv @ W_x -> g_xdbl
    xdbl_kernel<<<L_SEQ / 4, 128>>>(W_x);
    // 4) delta = softplus(dt @ W_dt + b_dt)
    {
        dim3 grid(DINNER / 256, L_SEQ / 16);
        delta_kernel<<<grid, 256>>>(W_dt, b_dt);
    }
    // 5) selective scan + skip + gate -> g_yg
    scan_kernel<<<(DINNER * NSTATE) / 256, 256>>>(A_log, Dv);
    // 6) yg @ W_out -> out  (M=1024, N=1024, K=2048)
    {
        dim3 grid(DMODEL / 128, L_SEQ / 128);
        sgemm128<1><<<grid, 256>>>(yg, W_out, out, L_SEQ, DMODEL, DINNER);
    }
}

// round 4
// speedup vs baseline: 1.2708x; 1.2708x over previous
#include <cuda_runtime.h>
#include <cuda_bf16.h>
#include <cstdint>

// ---------------- problem constants ----------------
#define L_SEQ   1024
#define DMODEL  1024
#define DINNER  2048
#define NSTATE  16
#define DTRANK  64
#define XDBL_W  96        // DTRANK + 2*NSTATE
#define WIN_N   4096      // 2*DINNER

// ---------------- scratch (__device__ globals; no allocation) ----------------
__device__ float g_xr[L_SEQ * WIN_N];        // x @ W_in   [1024,4096]
__device__ float g_xc[L_SEQ * DINNER];       // silu(conv) [1024,2048]
__device__ float g_xdbl[L_SEQ * XDBL_W];     // [1024,96]
__device__ float g_delta[L_SEQ * DINNER];    // [1024,2048]
__device__ float g_yg[L_SEQ * DINNER];       // gated scan output [1024,2048]
__device__ float g_WinT[WIN_N * DMODEL];     // W_in^T  [4096,1024]
__device__ float g_WoutT[DMODEL * DINNER];   // W_out^T [1024,2048]

// ---------------- tf32 helpers (base sm_103-legal PTX: sm_80 features) ------
__device__ __forceinline__ uint32_t f32_to_tf32(float x) {
    uint32_t y;
    asm("cvt.rna.tf32.f32 %0, %1;" : "=r"(y) : "f"(x));
    return y;
}

// D += A(m16k8) * B(k8n8), tf32 inputs, fp32 accum
__device__ __forceinline__ void mma_m16n8k8(float* d, const uint32_t* a, const uint32_t* b) {
    asm volatile(
        "mma.sync.aligned.m16n8k8.row.col.f32.tf32.tf32.f32 "
        "{%0,%1,%2,%3}, {%4,%5,%6,%7}, {%8,%9}, {%0,%1,%2,%3};"
        : "+f"(d[0]), "+f"(d[1]), "+f"(d[2]), "+f"(d[3])
        : "r"(a[0]), "r"(a[1]), "r"(a[2]), "r"(a[3]), "r"(b[0]), "r"(b[1]));
}

// ================= tf32 mma.sync GEMM =================
// C[M,N] = A[M,K] @ BT[N,K]^T, fp32 row-major. BK=16, double-buffered smem.
// 256 threads = 8 warps, layout WARPS_M x WARPS_N; warp tile (BM/WARPS_M)x(BN/WARPS_N).
template<int BM, int BN, int WARPS_M, int WARPS_N>
__global__ __launch_bounds__(256) void gemm_tf32_mma(const float* __restrict__ A,
                                                     const float* __restrict__ BT,
                                                     float* __restrict__ C,
                                                     int K, int N) {
    constexpr int WM = BM / WARPS_M;       // 64
    constexpr int WN = BN / WARPS_N;       // 32 or 16
    constexpr int MT = WM / 16;            // m16 tiles per warp
    constexpr int NT = WN / 8;             // n8 tiles per warp
    constexpr int SAP = BM + 4;            // padded smem strides
    constexpr int SBP = BN + 4;
    constexpr int NAV = BM / 64;           // float4 loads per thread for A
    constexpr int NBV = BN / 64;           // ... for B

    __shared__ uint32_t As[2][16][SAP];    // k-major: As[k][m]
    __shared__ uint32_t Bs[2][16][SBP];    // k-major: Bs[k][n]

    const int tid  = threadIdx.x;
    const int wid  = tid >> 5;
    const int lane = tid & 31;
    const int wm   = wid % WARPS_M;
    const int wn   = wid / WARPS_M;
    const int blockRow = blockIdx.y * BM;
    const int blockCol = blockIdx.x * BN;

    float4 aReg[NAV], bReg[NBV];

    auto gload = [&](int k0) {
        #pragma unroll
        for (int i = 0; i < NAV; i++) {
            int f = tid + i * 256;              // float4 idx over BM x 16 tile
            int row = f >> 2, kk = (f & 3) * 4;
            aReg[i] = *reinterpret_cast<const float4*>(&A[(size_t)(blockRow + row) * K + k0 + kk]);
        }
        #pragma unroll
        for (int i = 0; i < NBV; i++) {
            int f = tid + i * 256;
            int row = f >> 2, kk = (f & 3) * 4;
            bReg[i] = *reinterpret_cast<const float4*>(&BT[(size_t)(blockCol + row) * K + k0 + kk]);
        }
    };
    auto sstore = [&](int buf) {
        #pragma unroll
        for (int i = 0; i < NAV; i++) {
            int f = tid + i * 256;
            int row = f >> 2, kk = (f & 3) * 4;
            As[buf][kk + 0][row] = f32_to_tf32(aReg[i].x);
            As[buf][kk + 1][row] = f32_to_tf32(aReg[i].y);
            As[buf][kk + 2][row] = f32_to_tf32(aReg[i].z);
            As[buf][kk + 3][row] = f32_to_tf32(aReg[i].w);
        }
        #pragma unroll
        for (int i = 0; i < NBV; i++) {
            int f = tid + i * 256;
            int row = f >> 2, kk = (f & 3) * 4;
            Bs[buf][kk + 0][row] = f32_to_tf32(bReg[i].x);
            Bs[buf][kk + 1][row] = f32_to_tf32(bReg[i].y);
            Bs[buf][kk + 2][row] = f32_to_tf32(bReg[i].z);
            Bs[buf][kk + 3][row] = f32_to_tf32(bReg[i].w);
        }
    };

    float acc[MT][NT][4];
    #pragma unroll
    for (int m = 0; m < MT; m++)
        #pragma unroll
        for (int n = 0; n < NT; n++)
            #pragma unroll
            for (int j = 0; j < 4; j++) acc[m][n][j] = 0.f;

    const int nk = K >> 4;
    gload(0);
    sstore(0);
    __syncthreads();

    for (int i = 0; i < nk; i++) {
        if (i + 1 < nk) gload((i + 1) << 4);
        const int buf = i & 1;
        #pragma unroll
        for (int s = 0; s < 2; s++) {          // two k8 slices in BK=16
            uint32_t af[MT][4], bf[NT][2];
            const int c  = s * 8 + (lane & 3);
            const int rq = lane >> 2;
            #pragma unroll
            for (int m = 0; m < MT; m++) {
                int row0 = wm * WM + m * 16 + rq;
                af[m][0] = As[buf][c][row0];
                af[m][1] = As[buf][c][row0 + 8];
                af[m][2] = As[buf][c + 4][row0];
                af[m][3] = As[buf][c + 4][row0 + 8];
            }
            #pragma unroll
            for (int n = 0; n < NT; n++) {
                int coln = wn * WN + n * 8 + rq;
                bf[n][0] = Bs[buf][c][coln];
                bf[n][1] = Bs[buf][c + 4][coln];
            }
            #pragma unroll
            for (int m = 0; m < MT; m++)
                #pragma unroll
                for (int n = 0; n < NT; n++)
                    mma_m16n8k8(acc[m][n], af[m], bf[n]);
        }
        __syncthreads();
        if (i + 1 < nk) {
            sstore((i + 1) & 1);
            __syncthreads();
        }
    }

    // epilogue: C fragment layout m16n8: (row=lane>>2, col=(lane&3)*2)
    const int rq = lane >> 2, cq = (lane & 3) * 2;
    #pragma unroll
    for (int m = 0; m < MT; m++) {
        #pragma unroll
        for (int n = 0; n < NT; n++) {
            int row = blockRow + wm * WM + m * 16 + rq;
            int col = blockCol + wn * WN + n * 8 + cq;
            *reinterpret_cast<float2*>(&C[(size_t)row * N + col]) =
                make_float2(acc[m][n][0], acc[m][n][1]);
            *reinterpret_cast<float2*>(&C[(size_t)(row + 8) * N + col]) =
                make_float2(acc[m][n][2], acc[m][n][3]);
        }
    }
}

// ---------------- 32x32 tiled transpose: out[C,R] = in[R,C]^T ---------------
__global__ __launch_bounds__(256) void transpose32(const float* __restrict__ in,
                                                   float* __restrict__ out,
                                                   int R, int C) {
    __shared__ float tile[32][33];
    const int c0 = blockIdx.x * 32, r0 = blockIdx.y * 32;
    #pragma unroll
    for (int i = threadIdx.y; i < 32; i += 8)
        tile[i][threadIdx.x] = in[(size_t)(r0 + i) * C + c0 + threadIdx.x];
    __syncthreads();
    #pragma unroll
    for (int i = threadIdx.y; i < 32; i += 8)
        out[(size_t)(c0 + i) * R + r0 + threadIdx.x] = tile[threadIdx.x][i];
}

// ---------------- causal depthwise conv (K=4) + SiLU ------------------------
__global__ __launch_bounds__(256) void conv_silu_kernel(const float* __restrict__ conv_w,
                                                        const float* __restrict__ conv_b) {
    int idx = blockIdx.x * blockDim.x + threadIdx.x;   // t*2048 + d
    int t = idx >> 11;
    int d = idx & (DINNER - 1);
    float acc = conv_b[d];
    #pragma unroll
    for (int k = 0; k < 4; k++) {
        int tt = t - 3 + k;
        if (tt >= 0) acc = fmaf(g_xr[(size_t)tt * WIN_N + d], conv_w[d * 4 + k], acc);
    }
    float s = acc / (1.f + __expf(-acc));   // silu
    g_xc[idx] = s;
}

// ---------------- x_conv @ W_x -> x_dbl [1024,96] ---------------------------
__global__ __launch_bounds__(128) void xdbl_kernel(const float* __restrict__ Wx) {
    constexpr int TPER = 4;
    __shared__ float row[TPER * DINNER];   // 32 KB
    const int t0 = blockIdx.x * TPER;
    for (int i = threadIdx.x; i < TPER * DINNER; i += 128)
        row[i] = g_xc[(size_t)t0 * DINNER + i];
    __syncthreads();

    const int j = threadIdx.x;
    if (j < XDBL_W) {
        float acc[TPER] = {0.f, 0.f, 0.f, 0.f};
        #pragma unroll 4
        for (int k = 0; k < DINNER; k++) {
            float w = Wx[k * XDBL_W + j];
            #pragma unroll
            for (int tt = 0; tt < TPER; tt++)
                acc[tt] = fmaf(row[tt * DINNER + k], w, acc[tt]);
        }
        #pragma unroll
        for (int tt = 0; tt < TPER; tt++)
            g_xdbl[(size_t)(t0 + tt) * XDBL_W + j] = acc[tt];
    }
}

// ---------------- delta = softplus(dt @ W_dt + b_dt) ------------------------
__global__ __launch_bounds__(256) void delta_kernel(const float* __restrict__ Wdt,
                                                    const float* __restrict__ bdt) {
    constexpr int TPER = 16;
    __shared__ float sdt[TPER][DTRANK];
    const int d  = blockIdx.x * 256 + threadIdx.x;
    const int t0 = blockIdx.y * TPER;

    for (int i = threadIdx.x; i < TPER * DTRANK; i += 256) {
        int tt = i / DTRANK, k = i % DTRANK;
        sdt[tt][k] = g_xdbl[(size_t)(t0 + tt) * XDBL_W + k];
    }
    __syncthreads();

    float acc[TPER];
    float b = bdt[d];
    #pragma unroll
    for (int tt = 0; tt < TPER; tt++) acc[tt] = b;

    #pragma unroll 4
    for (int k = 0; k < DTRANK; k++) {
        float w = Wdt[k * DINNER + d];
        #pragma unroll
        for (int tt = 0; tt < TPER; tt++)
            acc[tt] = fmaf(sdt[tt][k], w, acc[tt]);
    }

    #pragma unroll
    for (int tt = 0; tt < TPER; tt++) {
        float x = acc[tt];
        float sp = (x > 20.f) ? x : log1pf(__expf(x));
        g_delta[(size_t)(t0 + tt) * DINNER + d] = sp;
    }
}

// ---------------- selective scan + skip + gate ------------------------------
__global__ __launch_bounds__(256) void scan_kernel(const float* __restrict__ A_log,
                                                   const float* __restrict__ Dvec) {
    const int gtid = blockIdx.x * blockDim.x + threadIdx.x;
    const int warp = gtid >> 5;
    const int lane = threadIdx.x & 31;
    const int grp  = lane >> 4;           // 0/1: which channel in warp
    const int n    = lane & 15;           // state index
    const int d    = warp * 2 + grp;      // channel 0..2047

    const float A  = -__expf(A_log[d * NSTATE + n]);
    const float Dd = Dvec[d];
    float h = 0.f;

    for (int t = 0; t < L_SEQ; t++) {
        const float dl = g_delta[(size_t)t * DINNER + d];
        const float u  = g_xc[(size_t)t * DINNER + d];
        const float Bn = g_xdbl[(size_t)t * XDBL_W + DTRANK + n];
        const float Cn = g_xdbl[(size_t)t * XDBL_W + DTRANK + NSTATE + n];

        const float dA = __expf(dl * A);
        h = fmaf(dA, h, dl * Bn * u);

        float p = h * Cn;
        p += __shfl_xor_sync(0xffffffffu, p, 8, 16);
        p += __shfl_xor_sync(0xffffffffu, p, 4, 16);
        p += __shfl_xor_sync(0xffffffffu, p, 2, 16);
        p += __shfl_xor_sync(0xffffffffu, p, 1, 16);

        if (n == 0) {
            const float r = g_xr[(size_t)t * WIN_N + DINNER + d];
            const float y = fmaf(u, Dd, p);
            const float gate = r / (1.f + __expf(-r));
            g_yg[(size_t)t * DINNER + d] = y * gate;
        }
    }
}

// ---------------- launcher ----------------
extern "C" void kernel_launch(void* const* d_in, const int* in_sizes, int n_in,
                              void* d_out, int out_size) {
    const float* x      = (const float*)d_in[0];   // [1,1024,1024]
    const float* W_in   = (const float*)d_in[1];   // [1024,4096]
    const float* conv_w = (const float*)d_in[2];   // [2048,4]
    const float* conv_b = (const float*)d_in[3];   // [2048]
    const float* W_x    = (const float*)d_in[4];   // [2048,96]
    const float* W_dt   = (const float*)d_in[5];   // [64,2048]
    const float* b_dt   = (const float*)d_in[6];   // [2048]
    const float* A_log  = (const float*)d_in[7];   // [2048,16]
    const float* Dv     = (const float*)d_in[8];   // [2048]
    const float* W_out  = (const float*)d_in[9];   // [2048,1024]
    float* out = (float*)d_out;                    // [1024,1024]

    float* xr;    cudaGetSymbolAddress((void**)&xr,    g_xr);
    float* yg;    cudaGetSymbolAddress((void**)&yg,    g_yg);
    float* winT;  cudaGetSymbolAddress((void**)&winT,  g_WinT);
    float* woutT; cudaGetSymbolAddress((void**)&woutT, g_WoutT);

    // 0) transpose weights for K-contiguous B loads
    {
        dim3 blk(32, 8);
        transpose32<<<dim3(WIN_N / 32, DMODEL / 32), blk>>>(W_in, winT, DMODEL, WIN_N);
        transpose32<<<dim3(DMODEL / 32, DINNER / 32), blk>>>(W_out, woutT, DINNER, DMODEL);
    }
    // 1) x @ W_in -> g_xr  (M=1024, N=4096, K=1024), tf32 mma.sync
    gemm_tf32_mma<128, 128, 2, 4><<<dim3(WIN_N / 128, L_SEQ / 128), 256>>>(x, winT, xr, DMODEL, WIN_N);
    // 2) causal conv + silu -> g_xc
    conv_silu_kernel<<<(L_SEQ * DINNER) / 256, 256>>>(conv_w, conv_b);
    // 3) x_conv @ W_x -> g_xdbl
    xdbl_kernel<<<L_SEQ / 4, 128>>>(W_x);
    // 4) delta = softplus(dt @ W_dt + b_dt)
    delta_kernel<<<dim3(DINNER / 256, L_SEQ / 16), 256>>>(W_dt, b_dt);
    // 5) selective scan + skip + gate -> g_yg
    scan_kernel<<<(DINNER * NSTATE) / 256, 256>>>(A_log, Dv);
    // 6) yg @ W_out -> out  (M=1024, N=1024, K=2048), tf32 mma.sync, 64-row tiles
    gemm_tf32_mma<64, 128, 1, 8><<<dim3(DMODEL / 128, L_SEQ / 64), 256>>>(yg, woutT, out, DINNER, DMODEL);
}

// round 5
// speedup vs baseline: 1.2835x; 1.0100x over previous
#include <cuda_runtime.h>
#include <cuda_bf16.h>
#include <cstdint>

// ---------------- problem constants ----------------
#define L_SEQ   1024
#define DMODEL  1024
#define DINNER  2048
#define NSTATE  16
#define DTRANK  64
#define XDBL_W  96        // DTRANK + 2*NSTATE
#define WIN_N   4096      // 2*DINNER

// ---------------- scratch (__device__ globals; no allocation) ----------------
__device__ float g_xr[L_SEQ * WIN_N];        // x @ W_in   [1024,4096]
__device__ float g_xc[L_SEQ * DINNER];       // silu(conv) [1024,2048]
__device__ float g_xdbl[L_SEQ * XDBL_W];     // [1024,96]
__device__ float g_delta[L_SEQ * DINNER];    // [1024,2048]
__device__ float g_yg[L_SEQ * DINNER];       // gated scan output [1024,2048]

// ---------------- PTX helpers (base sm_103-legal: sm_80 features only) ------
__device__ __forceinline__ uint32_t smem_u32(const void* p) {
    uint32_t a;
    asm("{ .reg .u64 t; cvta.to.shared.u64 t, %1; cvt.u32.u64 %0, t; }" : "=r"(a) : "l"(p));
    return a;
}
#define CP_ASYNC16(dst_u32, src_ptr) \
    asm volatile("cp.async.cg.shared.global [%0], [%1], 16;" \
                 :: "r"(dst_u32), "l"(src_ptr) : "memory")
#define CP_COMMIT() asm volatile("cp.async.commit_group;" ::: "memory")
#define CP_WAIT2()  asm volatile("cp.async.wait_group 2;" ::: "memory")

// split fp32 into tf32 hi + tf32 lo (3xTF32 trick)
__device__ __forceinline__ void split_tf32(float v, uint32_t& hi, uint32_t& lo) {
    asm("cvt.rna.tf32.f32 %0, %1;" : "=r"(hi) : "f"(v));
    float r = v - __uint_as_float(hi);
    asm("cvt.rna.tf32.f32 %0, %1;" : "=r"(lo) : "f"(r));
}

// D += A(m16k8) * B(k8n8), tf32 inputs, fp32 accum
__device__ __forceinline__ void mma_m16n8k8(float* d, const uint32_t* a, const uint32_t* b) {
    asm volatile(
        "mma.sync.aligned.m16n8k8.row.col.f32.tf32.tf32.f32 "
        "{%0,%1,%2,%3}, {%4,%5,%6,%7}, {%8,%9}, {%0,%1,%2,%3};"
        : "+f"(d[0]), "+f"(d[1]), "+f"(d[2]), "+f"(d[3])
        : "r"(a[0]), "r"(a[1]), "r"(a[2]), "r"(a[3]), "r"(b[0]), "r"(b[1]));
}

// ================= 3xTF32 mma.sync GEMM, cp.async 4-stage pipeline ==========
// C[M,N] = A[M,K] @ Bw[K,N], fp32 row-major (Bw n-contiguous: weights as-is).
// BN=128 fixed. 256 threads = 8 warps, WARPS_M x WARPS_N.
// Smem per stage: A [BM][20] (stride 20 -> conflict-free frag loads),
//                 B [16][136] (stride 136 == 8 mod 32 -> conflict-free).
template<int BM, int WARPS_M, int WARPS_N>
__global__ __launch_bounds__(256) void gemm_3xtf32(const float* __restrict__ A,
                                                   const float* __restrict__ Bw,
                                                   float* __restrict__ C,
                                                   int K, int N) {
    constexpr int BN = 128;
    constexpr int WM = BM / WARPS_M;
    constexpr int WN = BN / WARPS_N;
    constexpr int MT = WM / 16;
    constexpr int NT = WN / 8;
    constexpr int SA = BM * 20;            // A stage floats
    constexpr int SB = 16 * 136;           // B stage floats
    constexpr int SF = SA + SB;            // stage floats

    extern __shared__ float sm[];

    const int tid  = threadIdx.x;
    const int wid  = tid >> 5;
    const int lane = tid & 31;
    const int wm   = wid % WARPS_M;
    const int wn   = wid / WARPS_M;
    const int blockRow = blockIdx.y * BM;
    const int blockCol = blockIdx.x * BN;
    const int nk = K >> 4;

    auto issue = [&](int stage) {
        float* As_ = sm + (stage & 3) * SF;
        float* Bs_ = As_ + SA;
        const int k0 = stage << 4;
        #pragma unroll
        for (int c = tid; c < BM * 4; c += 256) {      // A: BM rows x 4 chunks of 16B
            int row = c >> 2, kc = (c & 3) * 4;
            CP_ASYNC16(smem_u32(As_ + row * 20 + kc),
                       &A[(size_t)(blockRow + row) * K + k0 + kc]);
        }
        #pragma unroll
        for (int c = tid; c < 512; c += 256) {         // B: 16 rows x 32 chunks of 16B
            int row = c >> 5, nc = (c & 31) * 4;
            CP_ASYNC16(smem_u32(Bs_ + row * 136 + nc),
                       &Bw[(size_t)(k0 + row) * N + blockCol + nc]);
        }
    };

    float acc[MT][NT][4];
    #pragma unroll
    for (int m = 0; m < MT; m++)
        #pragma unroll
        for (int n = 0; n < NT; n++)
            #pragma unroll
            for (int j = 0; j < 4; j++) acc[m][n][j] = 0.f;

    issue(0); CP_COMMIT();
    issue(1); CP_COMMIT();
    issue(2); CP_COMMIT();

    const int rq    = lane >> 2;
    const int cbase = lane & 3;

    for (int i = 0; i < nk; i++) {
        CP_WAIT2();
        __syncthreads();
        if (i + 3 < nk) issue(i + 3);
        CP_COMMIT();                       // always commit: keeps 3 groups pending

        const float* As_ = sm + (i & 3) * SF;
        const float* Bs_ = As_ + SA;

        #pragma unroll
        for (int s = 0; s < 2; s++) {
            const int c = s * 8 + cbase;
            uint32_t ah[MT][4], al[MT][4], bh[NT][2], bl[NT][2];
            #pragma unroll
            for (int m = 0; m < MT; m++) {
                int r0 = wm * WM + m * 16 + rq;
                split_tf32(As_[r0 * 20 + c],           ah[m][0], al[m][0]);
                split_tf32(As_[(r0 + 8) * 20 + c],     ah[m][1], al[m][1]);
                split_tf32(As_[r0 * 20 + c + 4],       ah[m][2], al[m][2]);
                split_tf32(As_[(r0 + 8) * 20 + c + 4], ah[m][3], al[m][3]);
            }
            #pragma unroll
            for (int n = 0; n < NT; n++) {
                int cn = wn * WN + n * 8 + rq;
                split_tf32(Bs_[c * 136 + cn],       bh[n][0], bl[n][0]);
                split_tf32(Bs_[(c + 4) * 136 + cn], bh[n][1], bl[n][1]);
            }
            #pragma unroll
            for (int m = 0; m < MT; m++)
                #pragma unroll
                for (int n = 0; n < NT; n++) {
                    mma_m16n8k8(acc[m][n], ah[m], bh[n]);   // hi*hi
                    mma_m16n8k8(acc[m][n], ah[m], bl[n]);   // hi*lo
                    mma_m16n8k8(acc[m][n], al[m], bh[n]);   // lo*hi
                }
        }
        __syncthreads();
    }

    // epilogue: m16n8 C fragment: (row=lane>>2, col=(lane&3)*2) and row+8
    const int cq = (lane & 3) * 2;
    #pragma unroll
    for (int m = 0; m < MT; m++)
        #pragma unroll
        for (int n = 0; n < NT; n++) {
            int row = blockRow + wm * WM + m * 16 + rq;
            int col = blockCol + wn * WN + n * 8 + cq;
            *reinterpret_cast<float2*>(&C[(size_t)row * N + col]) =
                make_float2(acc[m][n][0], acc[m][n][1]);
            *reinterpret_cast<float2*>(&C[(size_t)(row + 8) * N + col]) =
                make_float2(acc[m][n][2], acc[m][n][3]);
        }
}

// ---------------- causal depthwise conv (K=4) + SiLU ------------------------
__global__ __launch_bounds__(256) void conv_silu_kernel(const float* __restrict__ conv_w,
                                                        const float* __restrict__ conv_b) {
    int idx = blockIdx.x * blockDim.x + threadIdx.x;   // t*2048 + d
    int t = idx >> 11;
    int d = idx & (DINNER - 1);
    float acc = conv_b[d];
    #pragma unroll
    for (int k = 0; k < 4; k++) {
        int tt = t - 3 + k;
        if (tt >= 0) acc = fmaf(g_xr[(size_t)tt * WIN_N + d], conv_w[d * 4 + k], acc);
    }
    float s = acc / (1.f + __expf(-acc));   // silu
    g_xc[idx] = s;
}

// ---------------- x_conv @ W_x -> x_dbl [1024,96] ---------------------------
__global__ __launch_bounds__(128) void xdbl_kernel(const float* __restrict__ Wx) {
    constexpr int TPER = 4;
    __shared__ float row[TPER * DINNER];   // 32 KB
    const int t0 = blockIdx.x * TPER;
    for (int i = threadIdx.x; i < TPER * DINNER; i += 128)
        row[i] = g_xc[(size_t)t0 * DINNER + i];
    __syncthreads();

    const int j = threadIdx.x;
    if (j < XDBL_W) {
        float acc[TPER] = {0.f, 0.f, 0.f, 0.f};
        #pragma unroll 4
        for (int k = 0; k < DINNER; k++) {
            float w = Wx[k * XDBL_W + j];
            #pragma unroll
            for (int tt = 0; tt < TPER; tt++)
                acc[tt] = fmaf(row[tt * DINNER + k], w, acc[tt]);
        }
        #pragma unroll
        for (int tt = 0; tt < TPER; tt++)
            g_xdbl[(size_t)(t0 + tt) * XDBL_W + j] = acc[tt];
    }
}

// ---------------- delta = softplus(dt @ W_dt + b_dt) ------------------------
__global__ __launch_bounds__(256) void delta_kernel(const float* __restrict__ Wdt,
                                                    const float* __restrict__ bdt) {
    constexpr int TPER = 16;
    __shared__ float sdt[TPER][DTRANK];
    const int d  = blockIdx.x * 256 + threadIdx.x;
    const int t0 = blockIdx.y * TPER;

    for (int i = threadIdx.x; i < TPER * DTRANK; i += 256) {
        int tt = i / DTRANK, k = i % DTRANK;
        sdt[tt][k] = g_xdbl[(size_t)(t0 + tt) * XDBL_W + k];
    }
    __syncthreads();

    float acc[TPER];
    float b = bdt[d];
    #pragma unroll
    for (int tt = 0; tt < TPER; tt++) acc[tt] = b;

    #pragma unroll 4
    for (int k = 0; k < DTRANK; k++) {
        float w = Wdt[k * DINNER + d];
        #pragma unroll
        for (int tt = 0; tt < TPER; tt++)
            acc[tt] = fmaf(sdt[tt][k], w, acc[tt]);
    }

    #pragma unroll
    for (int tt = 0; tt < TPER; tt++) {
        float x = acc[tt];
        float sp = (x > 20.f) ? x : log1pf(__expf(x));
        g_delta[(size_t)(t0 + tt) * DINNER + d] = sp;
    }
}

// ---------------- selective scan + skip + gate ------------------------------
__global__ __launch_bounds__(256) void scan_kernel(const float* __restrict__ A_log,
                                                   const float* __restrict__ Dvec) {
    const int gtid = blockIdx.x * blockDim.x + threadIdx.x;
    const int warp = gtid >> 5;
    const int lane = threadIdx.x & 31;
    const int grp  = lane >> 4;           // 0/1: which channel in warp
    const int n    = lane & 15;           // state index
    const int d    = warp * 2 + grp;      // channel 0..2047

    const float A  = -__expf(A_log[d * NSTATE + n]);
    const float Dd = Dvec[d];
    float h = 0.f;

    for (int t = 0; t < L_SEQ; t++) {
        const float dl = g_delta[(size_t)t * DINNER + d];
        const float u  = g_xc[(size_t)t * DINNER + d];
        const float Bn = g_xdbl[(size_t)t * XDBL_W + DTRANK + n];
        const float Cn = g_xdbl[(size_t)t * XDBL_W + DTRANK + NSTATE + n];

        const float dA = __expf(dl * A);
        h = fmaf(dA, h, dl * Bn * u);

        float p = h * Cn;
        p += __shfl_xor_sync(0xffffffffu, p, 8, 16);
        p += __shfl_xor_sync(0xffffffffu, p, 4, 16);
        p += __shfl_xor_sync(0xffffffffu, p, 2, 16);
        p += __shfl_xor_sync(0xffffffffu, p, 1, 16);

        if (n == 0) {
            const float r = g_xr[(size_t)t * WIN_N + DINNER + d];
            const float y = fmaf(u, Dd, p);
            const float gate = r / (1.f + __expf(-r));
            g_yg[(size_t)t * DINNER + d] = y * gate;
        }
    }
}

// ---------------- launcher ----------------
extern "C" void kernel_launch(void* const* d_in, const int* in_sizes, int n_in,
                              void* d_out, int out_size) {
    const float* x      = (const float*)d_in[0];   // [1,1024,1024]
    const float* W_in   = (const float*)d_in[1];   // [1024,4096]  (K x N, n-contig)
    const float* conv_w = (const float*)d_in[2];   // [2048,4]
    const float* conv_b = (const float*)d_in[3];   // [2048]
    const float* W_x    = (const float*)d_in[4];   // [2048,96]
    const float* W_dt   = (const float*)d_in[5];   // [64,2048]
    const float* b_dt   = (const float*)d_in[6];   // [2048]
    const float* A_log  = (const float*)d_in[7];   // [2048,16]
    const float* Dv     = (const float*)d_in[8];   // [2048]
    const float* W_out  = (const float*)d_in[9];   // [2048,1024]  (K x N, n-contig)
    float* out = (float*)d_out;                    // [1024,1024]

    float* xr;  cudaGetSymbolAddress((void**)&xr, g_xr);
    float* yg;  cudaGetSymbolAddress((void**)&yg, g_yg);

    constexpr int SMEM1 = 4 * (128 * 20 + 16 * 136) * 4;   // 75776 B
    constexpr int SMEM4 = 4 * (64 * 20 + 16 * 136) * 4;    // 55296 B
    cudaFuncSetAttribute(gemm_3xtf32<128, 2, 4>, cudaFuncAttributeMaxDynamicSharedMemorySize, SMEM1);
    cudaFuncSetAttribute(gemm_3xtf32<64, 1, 8>,  cudaFuncAttributeMaxDynamicSharedMemorySize, SMEM4);

    // 1) x @ W_in -> g_xr  (M=1024, N=4096, K=1024)
    gemm_3xtf32<128, 2, 4><<<dim3(WIN_N / 128, L_SEQ / 128), 256, SMEM1>>>(x, W_in, xr, DMODEL, WIN_N);
    // 2) causal conv + silu -> g_xc
    conv_silu_kernel<<<(L_SEQ * DINNER) / 256, 256>>>(conv_w, conv_b);
    // 3) x_conv @ W_x -> g_xdbl
    xdbl_kernel<<<L_SEQ / 4, 128>>>(W_x);
    // 4) delta = softplus(dt @ W_dt + b_dt)
    delta_kernel<<<dim3(DINNER / 256, L_SEQ / 16), 256>>>(W_dt, b_dt);
    // 5) selective scan + skip + gate -> g_yg
    scan_kernel<<<(DINNER * NSTATE) / 256, 256>>>(A_log, Dv);
    // 6) yg @ W_out -> out  (M=1024, N=1024, K=2048), 64-row tiles for full-chip grid
    gemm_3xtf32<64, 1, 8><<<dim3(DMODEL / 128, L_SEQ / 64), 256, SMEM4>>>(yg, W_out, out, DINNER, DMODEL);
}

// round 12
// speedup vs baseline: 1.4450x; 1.1259x over previous
#include <cuda_runtime.h>
#include <cuda_fp16.h>
#include <cstdint>

// ---------------- problem constants ----------------
#define L_SEQ   1024
#define DMODEL  1024
#define DINNER  2048
#define NSTATE  16
#define DTRANK  64
#define XDBL_W  96        // DTRANK + 2*NSTATE
#define WIN_N   4096      // 2*DINNER

// ---------------- scratch (__device__ globals; no allocation) ----------------
__device__ float g_xr[L_SEQ * WIN_N];        // x @ W_in   [1024,4096]
__device__ float g_xc[L_SEQ * DINNER];       // silu(conv) [1024,2048]
__device__ float g_xdbl[L_SEQ * XDBL_W];     // [1024,96]
__device__ float g_delta[L_SEQ * DINNER];    // [1024,2048]
__device__ float g_yg[L_SEQ * DINNER];       // gated scan output [1024,2048]

// ---------------- PTX helpers (base sm_103-legal: sm_80 features only) ------
__device__ __forceinline__ uint32_t smem_u32(const void* p) {
    uint32_t a;
    asm("{ .reg .u64 t; cvta.to.shared.u64 t, %1; cvt.u32.u64 %0, t; }" : "=r"(a) : "l"(p));
    return a;
}
#define CP_ASYNC16(dst_u32, src_ptr) \
    asm volatile("cp.async.cg.shared.global [%0], [%1], 16;" \
                 :: "r"(dst_u32), "l"(src_ptr) : "memory")
#define CP_COMMIT() asm volatile("cp.async.commit_group;" ::: "memory")
#define CP_WAIT2()  asm volatile("cp.async.wait_group 2;" ::: "memory")

// D += A(m16k16) * B(k16n8), fp16 inputs, fp32 accum
__device__ __forceinline__ void mma_m16n8k16(float* d, const uint32_t* a, const uint32_t* b) {
    asm volatile(
        "mma.sync.aligned.m16n8k16.row.col.f32.f16.f16.f32 "
        "{%0,%1,%2,%3}, {%4,%5,%6,%7}, {%8,%9}, {%0,%1,%2,%3};"
        : "+f"(d[0]), "+f"(d[1]), "+f"(d[2]), "+f"(d[3])
        : "r"(a[0]), "r"(a[1]), "r"(a[2]), "r"(a[3]), "r"(b[0]), "r"(b[1]));
}

// split two f32 into packed half2 hi + half2 lo (Ootomo fp16 split-2)
__device__ __forceinline__ void split_pack(float v0, float v1, uint32_t& hi, uint32_t& lo) {
    __half h0 = __float2half_rn(v0), h1 = __float2half_rn(v1);
    __half l0 = __float2half_rn(v0 - __half2float(h0));
    __half l1 = __float2half_rn(v1 - __half2float(h1));
    __half2 hh = __halves2half2(h0, h1);
    __half2 ll = __halves2half2(l0, l1);
    hi = *reinterpret_cast<uint32_t*>(&hh);
    lo = *reinterpret_cast<uint32_t*>(&ll);
}

// no-op kernel: shifts launch positions so ncu's capture slot (4th launch)
// lands on the big GEMM.
__global__ void noop_kernel() {}

// ============ fp16-split-2 mma.sync GEMM, cp.async 4-stage (R5 dataflow) ====
// C[M,N] = A[M,K] @ Bw[K,N], fp32 row-major (Bw n-contiguous: weights as-is).
// BN=128, BK=16. 256 threads = 8 warps, WARPS_M x WARPS_N.
// Smem per stage: A m-major [BM][20] (f32), B [16][132] (f32; 132 == 4 mod 32
// -> conflict-free scalar frag loads at k=2cc,2cc+1,+8).
template<int BM, int WARPS_M, int WARPS_N>
__global__ __launch_bounds__(256) void gemm_fp16s(const float* __restrict__ A,
                                                  const float* __restrict__ Bw,
                                                  float* __restrict__ C,
                                                  int K, int N) {
    constexpr int BN  = 128;
    constexpr int WM  = BM / WARPS_M;
    constexpr int WN  = BN / WARPS_N;
    constexpr int MT  = WM / 16;
    constexpr int NT  = WN / 8;
    constexpr int SAP = 20;                 // A row stride (floats)
    constexpr int SBP = 132;                // B row stride (floats)
    constexpr int SAF = BM * SAP;
    constexpr int SBF = 16 * SBP;
    constexpr int SF  = SAF + SBF;          // floats per stage

    extern __shared__ float sm[];

    const int tid  = threadIdx.x;
    const int wid  = tid >> 5;
    const int lane = tid & 31;
    const int wm   = wid % WARPS_M;
    const int wn   = wid / WARPS_M;
    const int blockRow = blockIdx.y * BM;
    const int blockCol = blockIdx.x * BN;
    const int nk = K >> 4;

    auto issue = [&](int stage) {
        float* As_ = sm + (stage & 3) * SF;
        float* Bs_ = As_ + SAF;
        const int k0 = stage << 4;
        #pragma unroll
        for (int c = tid; c < BM * 4; c += 256) {      // A: BM rows x 4 x 16B
            int row = c >> 2, kc = (c & 3) * 4;
            CP_ASYNC16(smem_u32(As_ + row * SAP + kc),
                       &A[(size_t)(blockRow + row) * K + k0 + kc]);
        }
        #pragma unroll
        for (int c = tid; c < 512; c += 256) {         // B: 16 rows x 32 x 16B
            int row = c >> 5, nc = (c & 31) * 4;
            CP_ASYNC16(smem_u32(Bs_ + row * SBP + nc),
                       &Bw[(size_t)(k0 + row) * N + blockCol + nc]);
        }
    };

    float acc[MT][NT][4];
    #pragma unroll
    for (int m = 0; m < MT; m++)
        #pragma unroll
        for (int n = 0; n < NT; n++)
            #pragma unroll
            for (int j = 0; j < 4; j++) acc[m][n][j] = 0.f;

    issue(0); CP_COMMIT();
    issue(1); CP_COMMIT();
    issue(2); CP_COMMIT();

    const int rq = lane >> 2;
    const int cc = lane & 3;

    for (int i = 0; i < nk; i++) {
        CP_WAIT2();
        __syncthreads();                   // own-wait + barrier => all stage-i data visible
        if (i + 3 < nk) issue(i + 3);
        CP_COMMIT();                       // always commit: keeps 3 groups pending

        const float* As_ = sm + (i & 3) * SF;
        const float* Bs_ = As_ + SAF;

        uint32_t ah[MT][4], al[MT][4], bh[NT][2], bl[NT][2];
        #pragma unroll
        for (int m = 0; m < MT; m++) {
            int r0 = wm * WM + m * 16 + rq;
            float2 v0 = *reinterpret_cast<const float2*>(As_ + r0 * SAP + 2 * cc);
            float2 v1 = *reinterpret_cast<const float2*>(As_ + (r0 + 8) * SAP + 2 * cc);
            float2 v2 = *reinterpret_cast<const float2*>(As_ + r0 * SAP + 2 * cc + 8);
            float2 v3 = *reinterpret_cast<const float2*>(As_ + (r0 + 8) * SAP + 2 * cc + 8);
            split_pack(v0.x, v0.y, ah[m][0], al[m][0]);
            split_pack(v1.x, v1.y, ah[m][1], al[m][1]);
            split_pack(v2.x, v2.y, ah[m][2], al[m][2]);
            split_pack(v3.x, v3.y, ah[m][3], al[m][3]);
        }
        #pragma unroll
        for (int n = 0; n < NT; n++) {
            int cn = wn * WN + n * 8 + rq;
            float b0 = Bs_[(2 * cc) * SBP + cn];
            float b1 = Bs_[(2 * cc + 1) * SBP + cn];
            float b2 = Bs_[(2 * cc + 8) * SBP + cn];
            float b3 = Bs_[(2 * cc + 9) * SBP + cn];
            split_pack(b0, b1, bh[n][0], bl[n][0]);
            split_pack(b2, b3, bh[n][1], bl[n][1]);
        }
        #pragma unroll
        for (int m = 0; m < MT; m++)
            #pragma unroll
            for (int n = 0; n < NT; n++) {
                mma_m16n8k16(acc[m][n], ah[m], bh[n]);   // hi*hi
                mma_m16n8k16(acc[m][n], ah[m], bl[n]);   // hi*lo
                mma_m16n8k16(acc[m][n], al[m], bh[n]);   // lo*hi
            }
        __syncthreads();                   // protect stage reuse by issue(i+4)
    }

    // epilogue: m16n8 C fragment: (row=lane>>2, col=(lane&3)*2) and row+8
    const int cq = (lane & 3) * 2;
    #pragma unroll
    for (int m = 0; m < MT; m++)
        #pragma unroll
        for (int n = 0; n < NT; n++) {
            int row = blockRow + wm * WM + m * 16 + rq;
            int col = blockCol + wn * WN + n * 8 + cq;
            *reinterpret_cast<float2*>(&C[(size_t)row * N + col]) =
                make_float2(acc[m][n][0], acc[m][n][1]);
            *reinterpret_cast<float2*>(&C[(size_t)(row + 8) * N + col]) =
                make_float2(acc[m][n][2], acc[m][n][3]);
        }
}

// ---------------- causal depthwise conv (K=4) + SiLU ------------------------
__global__ __launch_bounds__(256) void conv_silu_kernel(const float* __restrict__ conv_w,
                                                        const float* __restrict__ conv_b) {
    int idx = blockIdx.x * blockDim.x + threadIdx.x;   // t*2048 + d
    int t = idx >> 11;
    int d = idx & (DINNER - 1);
    float acc = conv_b[d];
    #pragma unroll
    for (int k = 0; k < 4; k++) {
        int tt = t - 3 + k;
        if (tt >= 0) acc = fmaf(g_xr[(size_t)tt * WIN_N + d], conv_w[d * 4 + k], acc);
    }
    float s = acc / (1.f + __expf(-acc));   // silu
    g_xc[idx] = s;
}

// ---------------- x_conv @ W_x -> x_dbl [1024,96] ---------------------------
__global__ __launch_bounds__(128) void xdbl_kernel(const float* __restrict__ Wx) {
    constexpr int TPER = 4;
    __shared__ float row[TPER * DINNER];   // 32 KB
    const int t0 = blockIdx.x * TPER;
    for (int i = threadIdx.x; i < TPER * DINNER; i += 128)
        row[i] = g_xc[(size_t)t0 * DINNER + i];
    __syncthreads();

    const int j = threadIdx.x;
    if (j < XDBL_W) {
        float acc[TPER] = {0.f, 0.f, 0.f, 0.f};
        #pragma unroll 4
        for (int k = 0; k < DINNER; k++) {
            float w = Wx[k * XDBL_W + j];
            #pragma unroll
            for (int tt = 0; tt < TPER; tt++)
                acc[tt] = fmaf(row[tt * DINNER + k], w, acc[tt]);
        }
        #pragma unroll
        for (int tt = 0; tt < TPER; tt++)
            g_xdbl[(size_t)(t0 + tt) * XDBL_W + j] = acc[tt];
    }
}

// ---------------- delta = softplus(dt @ W_dt + b_dt) ------------------------
__global__ __launch_bounds__(256) void delta_kernel(const float* __restrict__ Wdt,
                                                    const float* __restrict__ bdt) {
    constexpr int TPER = 16;
    __shared__ float sdt[TPER][DTRANK];
    const int d  = blockIdx.x * 256 + threadIdx.x;
    const int t0 = blockIdx.y * TPER;

    for (int i = threadIdx.x; i < TPER * DTRANK; i += 256) {
        int tt = i / DTRANK, k = i % DTRANK;
        sdt[tt][k] = g_xdbl[(size_t)(t0 + tt) * XDBL_W + k];
    }
    __syncthreads();

    float acc[TPER];
    float b = bdt[d];
    #pragma unroll
    for (int tt = 0; tt < TPER; tt++) acc[tt] = b;

    #pragma unroll 4
    for (int k = 0; k < DTRANK; k++) {
        float w = Wdt[k * DINNER + d];
        #pragma unroll
        for (int tt = 0; tt < TPER; tt++)
            acc[tt] = fmaf(sdt[tt][k], w, acc[tt]);
    }

    #pragma unroll
    for (int tt = 0; tt < TPER; tt++) {
        float x = acc[tt];
        float sp = (x > 20.f) ? x : log1pf(__expf(x));
        g_delta[(size_t)(t0 + tt) * DINNER + d] = sp;
    }
}

// ---------------- selective scan + skip + gate ------------------------------
__global__ __launch_bounds__(256) void scan_kernel(const float* __restrict__ A_log,
                                                   const float* __restrict__ Dvec) {
    const int gtid = blockIdx.x * blockDim.x + threadIdx.x;
    const int warp = gtid >> 5;
    const int lane = threadIdx.x & 31;
    const int grp  = lane >> 4;           // 0/1: which channel in warp
    const int n    = lane & 15;           // state index
    const int d    = warp * 2 + grp;      // channel 0..2047

    const float A  = -__expf(A_log[d * NSTATE + n]);
    const float Dd = Dvec[d];
    float h = 0.f;

    for (int t = 0; t < L_SEQ; t++) {
        const float dl = g_delta[(size_t)t * DINNER + d];
        const float u  = g_xc[(size_t)t * DINNER + d];
        const float Bn = g_xdbl[(size_t)t * XDBL_W + DTRANK + n];
        const float Cn = g_xdbl[(size_t)t * XDBL_W + DTRANK + NSTATE + n];

        const float dA = __expf(dl * A);
        h = fmaf(dA, h, dl * Bn * u);

        float p = h * Cn;
        p += __shfl_xor_sync(0xffffffffu, p, 8, 16);
        p += __shfl_xor_sync(0xffffffffu, p, 4, 16);
        p += __shfl_xor_sync(0xffffffffu, p, 2, 16);
        p += __shfl_xor_sync(0xffffffffu, p, 1, 16);

        if (n == 0) {
            const float r = g_xr[(size_t)t * WIN_N + DINNER + d];
            const float y = fmaf(u, Dd, p);
            const float gate = r / (1.f + __expf(-r));
            g_yg[(size_t)t * DINNER + d] = y * gate;
        }
    }
}

// ---------------- launcher ----------------
extern "C" void kernel_launch(void* const* d_in, const int* in_sizes, int n_in,
                              void* d_out, int out_size) {
    const float* x      = (const float*)d_in[0];   // [1,1024,1024]
    const float* W_in   = (const float*)d_in[1];   // [1024,4096]  (K x N, n-contig)
    const float* conv_w = (const float*)d_in[2];   // [2048,4]
    const float* conv_b = (const float*)d_in[3];   // [2048]
    const float* W_x    = (const float*)d_in[4];   // [2048,96]
    const float* W_dt   = (const float*)d_in[5];   // [64,2048]
    const float* b_dt   = (const float*)d_in[6];   // [2048]
    const float* A_log  = (const float*)d_in[7];   // [2048,16]
    const float* Dv     = (const float*)d_in[8];   // [2048]
    const float* W_out  = (const float*)d_in[9];   // [2048,1024]  (K x N, n-contig)
    float* out = (float*)d_out;                    // [1024,1024]

    float* xr;  cudaGetSymbolAddress((void**)&xr, g_xr);
    float* yg;  cudaGetSymbolAddress((void**)&yg, g_yg);

    // smem: 4 stages of (BM*20 + 16*132) f32
    constexpr int SMEM1 = 4 * (128 * 20 + 16 * 132) * 4;   // 74752 B
    constexpr int SMEM4 = 4 * (64 * 20 + 16 * 132) * 4;    // 54272 B
    cudaFuncSetAttribute(gemm_fp16s<128, 2, 4>, cudaFuncAttributeMaxDynamicSharedMemorySize, SMEM1);
    cudaFuncSetAttribute(gemm_fp16s<64, 1, 8>,  cudaFuncAttributeMaxDynamicSharedMemorySize, SMEM4);

    // 0) three no-op launches: put gemm1 in the ncu capture slot (4th launch)
    noop_kernel<<<1, 32>>>();
    noop_kernel<<<1, 32>>>();
    noop_kernel<<<1, 32>>>();
    // 1) x @ W_in -> g_xr  (M=1024, N=4096, K=1024)
    gemm_fp16s<128, 2, 4><<<dim3(WIN_N / 128, L_SEQ / 128), 256, SMEM1>>>(x, W_in, xr, DMODEL, WIN_N);
    // 2) causal conv + silu -> g_xc
    conv_silu_kernel<<<(L_SEQ * DINNER) / 256, 256>>>(conv_w, conv_b);
    // 3) x_conv @ W_x -> g_xdbl
    xdbl_kernel<<<L_SEQ / 4, 128>>>(W_x);
    // 4) delta = softplus(dt @ W_dt + b_dt)
    delta_kernel<<<dim3(DINNER / 256, L_SEQ / 16), 256>>>(W_dt, b_dt);
    // 5) selective scan + skip + gate -> g_yg
    scan_kernel<<<(DINNER * NSTATE) / 256, 256>>>(A_log, Dv);
    // 6) yg @ W_out -> out  (M=1024, N=1024, K=2048), 64-row tiles
    gemm_fp16s<64, 1, 8><<<dim3(DMODEL / 128, L_SEQ / 64), 256, SMEM4>>>(yg, W_out, out, DINNER, DMODEL);
}

// round 15
// speedup vs baseline: 2.7773x; 1.9220x over previous
#include <cuda_runtime.h>
#include <cuda_fp16.h>
#include <cstdint>

// ---------------- problem constants ----------------
#define L_SEQ   1024
#define DMODEL  1024
#define DINNER  2048
#define NSTATE  16
#define DTRANK  64
#define XDBL_W  96        // DTRANK + 2*NSTATE
#define WIN_N   4096      // 2*DINNER
#define NCHUNK  16
#define CHLEN   64        // L_SEQ / NCHUNK

// ---------------- scratch (__device__ globals; no allocation) ----------------
__device__ float g_xr[L_SEQ * WIN_N];        // x @ W_in   [1024,4096]
__device__ float g_xc[L_SEQ * DINNER];       // silu(conv) [1024,2048]
__device__ float g_xdbl[L_SEQ * XDBL_W];     // [1024,96]
__device__ float g_delta[L_SEQ * DINNER];    // [1024,2048]
__device__ float g_yg[L_SEQ * DINNER];       // gated scan output [1024,2048]
__device__ float g_Ac[NCHUNK * DINNER * NSTATE];  // chunk decay products
__device__ float g_Bc[NCHUNK * DINNER * NSTATE];  // chunk local results
__device__ float g_h0[NCHUNK * DINNER * NSTATE];  // chunk entry states

// ---------------- PTX helpers (base sm_103-legal: sm_80 features only) ------
__device__ __forceinline__ uint32_t smem_u32(const void* p) {
    uint32_t a;
    asm("{ .reg .u64 t; cvta.to.shared.u64 t, %1; cvt.u32.u64 %0, t; }" : "=r"(a) : "l"(p));
    return a;
}
#define CP_ASYNC16(dst_u32, src_ptr) \
    asm volatile("cp.async.cg.shared.global [%0], [%1], 16;" \
                 :: "r"(dst_u32), "l"(src_ptr) : "memory")
#define CP_COMMIT() asm volatile("cp.async.commit_group;" ::: "memory")
#define CP_WAIT2()  asm volatile("cp.async.wait_group 2;" ::: "memory")

// D += A(m16k16) * B(k16n8), fp16 inputs, fp32 accum
__device__ __forceinline__ void mma_m16n8k16(float* d, const uint32_t* a, const uint32_t* b) {
    asm volatile(
        "mma.sync.aligned.m16n8k16.row.col.f32.f16.f16.f32 "
        "{%0,%1,%2,%3}, {%4,%5,%6,%7}, {%8,%9}, {%0,%1,%2,%3};"
        : "+f"(d[0]), "+f"(d[1]), "+f"(d[2]), "+f"(d[3])
        : "r"(a[0]), "r"(a[1]), "r"(a[2]), "r"(a[3]), "r"(b[0]), "r"(b[1]));
}

// split two f32 into packed half2 hi + half2 lo (Ootomo fp16 split-2)
__device__ __forceinline__ void split_pack(float v0, float v1, uint32_t& hi, uint32_t& lo) {
    __half h0 = __float2half_rn(v0), h1 = __float2half_rn(v1);
    __half l0 = __float2half_rn(v0 - __half2float(h0));
    __half l1 = __float2half_rn(v1 - __half2float(h1));
    __half2 hh = __halves2half2(h0, h1);
    __half2 ll = __halves2half2(l0, l1);
    hi = *reinterpret_cast<uint32_t*>(&hh);
    lo = *reinterpret_cast<uint32_t*>(&ll);
}

// ============ fp16-split-2 mma.sync GEMM, cp.async 4-stage ==================
template<int BM, int WARPS_M, int WARPS_N>
__global__ __launch_bounds__(256) void gemm_fp16s(const float* __restrict__ A,
                                                  const float* __restrict__ Bw,
                                                  float* __restrict__ C,
                                                  int K, int N) {
    constexpr int BN  = 128;
    constexpr int WM  = BM / WARPS_M;
    constexpr int WN  = BN / WARPS_N;
    constexpr int MT  = WM / 16;
    constexpr int NT  = WN / 8;
    constexpr int SAP = 20;                 // A row stride (floats)
    constexpr int SBP = 132;                // B row stride (floats)
    constexpr int SAF = BM * SAP;
    constexpr int SBF = 16 * SBP;
    constexpr int SF  = SAF + SBF;          // floats per stage

    extern __shared__ float sm[];

    const int tid  = threadIdx.x;
    const int wid  = tid >> 5;
    const int lane = tid & 31;
    const int wm   = wid % WARPS_M;
    const int wn   = wid / WARPS_M;
    const int blockRow = blockIdx.y * BM;
    const int blockCol = blockIdx.x * BN;
    const int nk = K >> 4;

    auto issue = [&](int stage) {
        float* As_ = sm + (stage & 3) * SF;
        float* Bs_ = As_ + SAF;
        const int k0 = stage << 4;
        #pragma unroll
        for (int c = tid; c < BM * 4; c += 256) {      // A: BM rows x 4 x 16B
            int row = c >> 2, kc = (c & 3) * 4;
            CP_ASYNC16(smem_u32(As_ + row * SAP + kc),
                       &A[(size_t)(blockRow + row) * K + k0 + kc]);
        }
        #pragma unroll
        for (int c = tid; c < 512; c += 256) {         // B: 16 rows x 32 x 16B
            int row = c >> 5, nc = (c & 31) * 4;
            CP_ASYNC16(smem_u32(Bs_ + row * SBP + nc),
                       &Bw[(size_t)(k0 + row) * N + blockCol + nc]);
        }
    };

    float acc[MT][NT][4];
    #pragma unroll
    for (int m = 0; m < MT; m++)
        #pragma unroll
        for (int n = 0; n < NT; n++)
            #pragma unroll
            for (int j = 0; j < 4; j++) acc[m][n][j] = 0.f;

    issue(0); CP_COMMIT();
    issue(1); CP_COMMIT();
    issue(2); CP_COMMIT();

    const int rq = lane >> 2;
    const int cc = lane & 3;

    for (int i = 0; i < nk; i++) {
        CP_WAIT2();
        __syncthreads();
        if (i + 3 < nk) issue(i + 3);
        CP_COMMIT();

        const float* As_ = sm + (i & 3) * SF;
        const float* Bs_ = As_ + SAF;

        uint32_t ah[MT][4], al[MT][4], bh[NT][2], bl[NT][2];
        #pragma unroll
        for (int m = 0; m < MT; m++) {
            int r0 = wm * WM + m * 16 + rq;
            float2 v0 = *reinterpret_cast<const float2*>(As_ + r0 * SAP + 2 * cc);
            float2 v1 = *reinterpret_cast<const float2*>(As_ + (r0 + 8) * SAP + 2 * cc);
            float2 v2 = *reinterpret_cast<const float2*>(As_ + r0 * SAP + 2 * cc + 8);
            float2 v3 = *reinterpret_cast<const float2*>(As_ + (r0 + 8) * SAP + 2 * cc + 8);
            split_pack(v0.x, v0.y, ah[m][0], al[m][0]);
            split_pack(v1.x, v1.y, ah[m][1], al[m][1]);
            split_pack(v2.x, v2.y, ah[m][2], al[m][2]);
            split_pack(v3.x, v3.y, ah[m][3], al[m][3]);
        }
        #pragma unroll
        for (int n = 0; n < NT; n++) {
            int cn = wn * WN + n * 8 + rq;
            float b0 = Bs_[(2 * cc) * SBP + cn];
            float b1 = Bs_[(2 * cc + 1) * SBP + cn];
            float b2 = Bs_[(2 * cc + 8) * SBP + cn];
            float b3 = Bs_[(2 * cc + 9) * SBP + cn];
            split_pack(b0, b1, bh[n][0], bl[n][0]);
            split_pack(b2, b3, bh[n][1], bl[n][1]);
        }
        #pragma unroll
        for (int m = 0; m < MT; m++)
            #pragma unroll
            for (int n = 0; n < NT; n++) {
                mma_m16n8k16(acc[m][n], ah[m], bh[n]);   // hi*hi
                mma_m16n8k16(acc[m][n], ah[m], bl[n]);   // hi*lo
                mma_m16n8k16(acc[m][n], al[m], bh[n]);   // lo*hi
            }
        __syncthreads();
    }

    const int cq = (lane & 3) * 2;
    #pragma unroll
    for (int m = 0; m < MT; m++)
        #pragma unroll
        for (int n = 0; n < NT; n++) {
            int row = blockRow + wm * WM + m * 16 + rq;
            int col = blockCol + wn * WN + n * 8 + cq;
            *reinterpret_cast<float2*>(&C[(size_t)row * N + col]) =
                make_float2(acc[m][n][0], acc[m][n][1]);
            *reinterpret_cast<float2*>(&C[(size_t)(row + 8) * N + col]) =
                make_float2(acc[m][n][2], acc[m][n][3]);
        }
}

// ---------------- causal depthwise conv (K=4) + SiLU ------------------------
__global__ __launch_bounds__(256) void conv_silu_kernel(const float* __restrict__ conv_w,
                                                        const float* __restrict__ conv_b) {
    int idx = blockIdx.x * blockDim.x + threadIdx.x;   // t*2048 + d
    int t = idx >> 11;
    int d = idx & (DINNER - 1);
    float acc = conv_b[d];
    #pragma unroll
    for (int k = 0; k < 4; k++) {
        int tt = t - 3 + k;
        if (tt >= 0) acc = fmaf(g_xr[(size_t)tt * WIN_N + d], conv_w[d * 4 + k], acc);
    }
    float s = acc / (1.f + __expf(-acc));   // silu
    g_xc[idx] = s;
}

// ---------------- x_conv @ W_x -> x_dbl [1024,96] ---------------------------
__global__ __launch_bounds__(128) void xdbl_kernel(const float* __restrict__ Wx) {
    constexpr int TPER = 4;
    __shared__ float row[TPER * DINNER];   // 32 KB
    const int t0 = blockIdx.x * TPER;
    for (int i = threadIdx.x; i < TPER * DINNER; i += 128)
        row[i] = g_xc[(size_t)t0 * DINNER + i];
    __syncthreads();

    const int j = threadIdx.x;
    if (j < XDBL_W) {
        float acc[TPER] = {0.f, 0.f, 0.f, 0.f};
        #pragma unroll 4
        for (int k = 0; k < DINNER; k++) {
            float w = Wx[k * XDBL_W + j];
            #pragma unroll
            for (int tt = 0; tt < TPER; tt++)
                acc[tt] = fmaf(row[tt * DINNER + k], w, acc[tt]);
        }
        #pragma unroll
        for (int tt = 0; tt < TPER; tt++)
            g_xdbl[(size_t)(t0 + tt) * XDBL_W + j] = acc[tt];
    }
}

// ---------------- delta = softplus(dt @ W_dt + b_dt) ------------------------
__global__ __launch_bounds__(256) void delta_kernel(const float* __restrict__ Wdt,
                                                    const float* __restrict__ bdt) {
    constexpr int TPER = 16;
    __shared__ float sdt[TPER][DTRANK];
    const int d  = blockIdx.x * 256 + threadIdx.x;
    const int t0 = blockIdx.y * TPER;

    for (int i = threadIdx.x; i < TPER * DTRANK; i += 256) {
        int tt = i / DTRANK, k = i % DTRANK;
        sdt[tt][k] = g_xdbl[(size_t)(t0 + tt) * XDBL_W + k];
    }
    __syncthreads();

    float acc[TPER];
    float b = bdt[d];
    #pragma unroll
    for (int tt = 0; tt < TPER; tt++) acc[tt] = b;

    #pragma unroll 4
    for (int k = 0; k < DTRANK; k++) {
        float w = Wdt[k * DINNER + d];
        #pragma unroll
        for (int tt = 0; tt < TPER; tt++)
            acc[tt] = fmaf(sdt[tt][k], w, acc[tt]);
    }

    #pragma unroll
    for (int tt = 0; tt < TPER; tt++) {
        float x = acc[tt];
        float sp = (x > 20.f) ? x : log1pf(__expf(x));
        g_delta[(size_t)(t0 + tt) * DINNER + d] = sp;
    }
}

// ---------------- chunked selective scan: pass 1 (local chunk scans) --------
// grid (DINNER*NSTATE/256, NCHUNK); thread -> (d, n) within chunk blockIdx.y
__global__ __launch_bounds__(256) void scan_pass1(const float* __restrict__ A_log) {
    const int warp = (blockIdx.x * 256 + threadIdx.x) >> 5;
    const int lane = threadIdx.x & 31;
    const int grp  = lane >> 4;
    const int n    = lane & 15;
    const int d    = warp * 2 + grp;
    const int c    = blockIdx.y;

    const float A = -__expf(A_log[d * NSTATE + n]);
    float h = 0.f, S = 0.f;
    const int t0 = c * CHLEN;
    for (int t = t0; t < t0 + CHLEN; t++) {
        const float dl = g_delta[(size_t)t * DINNER + d];
        const float u  = g_xc[(size_t)t * DINNER + d];
        const float Bn = g_xdbl[(size_t)t * XDBL_W + DTRANK + n];
        const float dA = __expf(dl * A);
        h = fmaf(dA, h, dl * Bn * u);
        S += dl;
    }
    const int idx = (c * DINNER + d) * NSTATE + n;
    g_Ac[idx] = __expf(A * S);     // product of exp(dl*A) over the chunk
    g_Bc[idx] = h;
}

// ---------------- pass 2: sequential combine across chunks -----------------
// 32768 threads, one per (d,n); 16-step loop
__global__ __launch_bounds__(256) void scan_pass2() {
    const int i = blockIdx.x * 256 + threadIdx.x;    // d*16+n
    float h = 0.f;
    #pragma unroll
    for (int c = 0; c < NCHUNK; c++) {
        const int idx = c * (DINNER * NSTATE) + i;
        g_h0[idx] = h;
        h = fmaf(g_Ac[idx], h, g_Bc[idx]);
    }
}

// ---------------- pass 3: full scan per chunk, seeded + output --------------
__global__ __launch_bounds__(256) void scan_pass3(const float* __restrict__ A_log,
                                                  const float* __restrict__ Dvec) {
    const int warp = (blockIdx.x * 256 + threadIdx.x) >> 5;
    const int lane = threadIdx.x & 31;
    const int grp  = lane >> 4;
    const int n    = lane & 15;
    const int d    = warp * 2 + grp;
    const int c    = blockIdx.y;

    const float A  = -__expf(A_log[d * NSTATE + n]);
    const float Dd = Dvec[d];
    float h = g_h0[(c * DINNER + d) * NSTATE + n];

    const int t0 = c * CHLEN;
    for (int t = t0; t < t0 + CHLEN; t++) {
        const float dl = g_delta[(size_t)t * DINNER + d];
        const float u  = g_xc[(size_t)t * DINNER + d];
        const float Bn = g_xdbl[(size_t)t * XDBL_W + DTRANK + n];
        const float Cn = g_xdbl[(size_t)t * XDBL_W + DTRANK + NSTATE + n];

        const float dA = __expf(dl * A);
        h = fmaf(dA, h, dl * Bn * u);

        float p = h * Cn;
        p += __shfl_xor_sync(0xffffffffu, p, 8, 16);
        p += __shfl_xor_sync(0xffffffffu, p, 4, 16);
        p += __shfl_xor_sync(0xffffffffu, p, 2, 16);
        p += __shfl_xor_sync(0xffffffffu, p, 1, 16);

        if (n == 0) {
            const float r = g_xr[(size_t)t * WIN_N + DINNER + d];
            const float y = fmaf(u, Dd, p);
            const float gate = r / (1.f + __expf(-r));
            g_yg[(size_t)t * DINNER + d] = y * gate;
        }
    }
}

// ---------------- launcher ----------------
extern "C" void kernel_launch(void* const* d_in, const int* in_sizes, int n_in,
                              void* d_out, int out_size) {
    const float* x      = (const float*)d_in[0];   // [1,1024,1024]
    const float* W_in   = (const float*)d_in[1];   // [1024,4096]  (K x N, n-contig)
    const float* conv_w = (const float*)d_in[2];   // [2048,4]
    const float* conv_b = (const float*)d_in[3];   // [2048]
    const float* W_x    = (const float*)d_in[4];   // [2048,96]
    const float* W_dt   = (const float*)d_in[5];   // [64,2048]
    const float* b_dt   = (const float*)d_in[6];   // [2048]
    const float* A_log  = (const float*)d_in[7];   // [2048,16]
    const float* Dv     = (const float*)d_in[8];   // [2048]
    const float* W_out  = (const float*)d_in[9];   // [2048,1024]  (K x N, n-contig)
    float* out = (float*)d_out;                    // [1024,1024]

    float* xr;  cudaGetSymbolAddress((void**)&xr, g_xr);
    float* yg;  cudaGetSymbolAddress((void**)&yg, g_yg);

    constexpr int SMEM1 = 4 * (128 * 20 + 16 * 132) * 4;   // 74752 B
    constexpr int SMEM4 = 4 * (64 * 20 + 16 * 132) * 4;    // 54272 B
    cudaFuncSetAttribute(gemm_fp16s<128, 2, 4>, cudaFuncAttributeMaxDynamicSharedMemorySize, SMEM1);
    cudaFuncSetAttribute(gemm_fp16s<64, 1, 8>,  cudaFuncAttributeMaxDynamicSharedMemorySize, SMEM4);

    // 1) x @ W_in -> g_xr  (M=1024, N=4096, K=1024)
    gemm_fp16s<128, 2, 4><<<dim3(WIN_N / 128, L_SEQ / 128), 256, SMEM1>>>(x, W_in, xr, DMODEL, WIN_N);
    // 2) causal conv + silu -> g_xc
    conv_silu_kernel<<<(L_SEQ * DINNER) / 256, 256>>>(conv_w, conv_b);
    // 3) x_conv @ W_x -> g_xdbl
    xdbl_kernel<<<L_SEQ / 4, 128>>>(W_x);
    // 4) delta = softplus(dt @ W_dt + b_dt)
    delta_kernel<<<dim3(DINNER / 256, L_SEQ / 16), 256>>>(W_dt, b_dt);
    // 5) chunked selective scan (3 passes) + skip + gate -> g_yg
    scan_pass1<<<dim3(DINNER * NSTATE / 256, NCHUNK), 256>>>(A_log);
    scan_pass2<<<DINNER * NSTATE / 256, 256>>>();
    scan_pass3<<<dim3(DINNER * NSTATE / 256, NCHUNK), 256>>>(A_log, Dv);
    // 6) yg @ W_out -> out  (M=1024, N=1024, K=2048)
    gemm_fp16s<64, 1, 8><<<dim3(DMODEL / 128, L_SEQ / 64), 256, SMEM4>>>(yg, W_out, out, DINNER, DMODEL);
}